// round 11
// baseline (speedup 1.0000x reference)
#include <cuda_runtime.h>
#include <cuda_bf16.h>
#include <cstdint>

// ---------------- problem constants ----------------
#define N_TOT 8192
#define D     128
#define IPC_C 512
#define ROW0  7680            // bz - IPC
#define NCOL  7680            // unmasked columns [0, 7680)
#define BM    128
#define BN    256
#define NTIL  (NCOL / BN)     // 30 column tiles
#define ETIL  (1024 / BN)     // tiles [0,4) = easy region (exact boundary)
#define NBLK  (NTIL * (IPC_C / BM))   // 120 blocks = one wave
#define LDB   136             // bf16 smem row stride; 272 bytes (16B-aligned)

// ---------------- device globals ----------------
__device__ __nv_bfloat16 g_bf[N_TOT * D];   // normalized bf16
__device__ float g_part[NTIL * IPC_C];      // [colTile][row] partial maxima
__device__ int   g_done;                    // zero-init; reset each replay

#define CP_ASYNC16(dst_u32, src_ptr) \
    asm volatile("cp.async.cg.shared.global [%0], [%1], 16;" \
                 :: "r"(dst_u32), "l"(src_ptr) : "memory")
#define CP_COMMIT()  asm volatile("cp.async.commit_group;" ::: "memory")
#define CP_WAIT0()   asm volatile("cp.async.wait_group 0;" ::: "memory")

#define LDSM_X4(r0, r1, r2, r3, addr) \
    asm volatile("ldmatrix.sync.aligned.m8n8.x4.shared.b16 {%0,%1,%2,%3}, [%4];" \
                 : "=r"(r0), "=r"(r1), "=r"(r2), "=r"(r3) : "r"(addr))

// ---------------- kernel 1: normalize -> bf16 (8 threads per row) ----------------
__global__ void __launch_bounds__(256) prep_kernel(const float* __restrict__ f) {
    const int t   = threadIdx.x;
    const int row = blockIdx.x * 32 + (t >> 3);
    const int l8  = t & 7;
    const float4* src = (const float4*)(f + (size_t)row * D);

    float4 v[4];
    float s = 0.f;
    #pragma unroll
    for (int j = 0; j < 4; j++) {
        v[j] = src[l8 + 8 * j];
        s += v[j].x * v[j].x + v[j].y * v[j].y + v[j].z * v[j].z + v[j].w * v[j].w;
    }
    #pragma unroll
    for (int o = 1; o < 8; o <<= 1) s += __shfl_xor_sync(0xffffffffu, s, o);
    float inv = rsqrtf(s);
    if (!(s > 1e-24f)) inv = 1e12f;

    #pragma unroll
    for (int j = 0; j < 4; j++) {
        __nv_bfloat162 p0 = __floats2bfloat162_rn(v[j].x * inv, v[j].y * inv);
        __nv_bfloat162 p1 = __floats2bfloat162_rn(v[j].z * inv, v[j].w * inv);
        uint2 packed = make_uint2(*(uint32_t*)&p0, *(uint32_t*)&p1);
        *(uint2*)(g_bf + (size_t)row * D + l8 * 4 + 32 * j) = packed;
    }
}

// ---------------- kernel 2: bf16 m16n8k16 GEMM, 1024 thr, ldmatrix ----------------
// 32 warps = 4(m) x 8(n); warp tile 32x32; 120 blocks, one wave.
// smem: A bf16[128][136] + B bf16[256][136] = 104448 B
#define SMEM_BYTES (BM * LDB * 2 + BN * LDB * 2)

__global__ void __launch_bounds__(1024, 1) gemm_kernel(const float* __restrict__ a_scl,
                                                       float* __restrict__ out) {
    extern __shared__ char smraw[];
    __nv_bfloat16* As = (__nv_bfloat16*)smraw;
    __nv_bfloat16* Bs = As + BM * LDB;

    const int tid  = threadIdx.x;
    const int lane = tid & 31;
    const int w    = tid >> 5;
    const int wm   = w >> 3;        // 0..3 -> 32-row strip
    const int wn   = w & 7;         // 0..7 -> 32-col strip
    const int q    = lane >> 2;     // 0..7
    const int rowBase = ROW0 + blockIdx.y * BM;
    const int colBase = blockIdx.x * BN;

    const uint32_t sA = (uint32_t)__cvta_generic_to_shared(As);
    const uint32_t sB = (uint32_t)__cvta_generic_to_shared(Bs);

    // ---- stage A (128 rows) and B (256 rows): 16B chunks, 16 per row ----
    #pragma unroll
    for (int t = 0; t < 2; t++) {                  // A: 2048 chunks
        int idx = tid + t * 1024;
        int r = idx >> 4, c = idx & 15;
        CP_ASYNC16(sA + r * (LDB * 2) + c * 16,
                   g_bf + (size_t)(rowBase + r) * D + c * 8);
    }
    #pragma unroll
    for (int t = 0; t < 4; t++) {                  // B: 4096 chunks
        int idx = tid + t * 1024;
        int r = idx >> 4, c = idx & 15;
        CP_ASYNC16(sB + r * (LDB * 2) + c * 16,
                   g_bf + (size_t)(colBase + r) * D + c * 8);
    }
    CP_COMMIT();
    CP_WAIT0();
    __syncthreads();

    // ---- ldmatrix lane base addresses ----
    // A x4 (per mt): m0=rows 0-7,k0-7 | m1=rows 8-15,k0-7 | m2=rows 0-7,k8-15 | m3=rows 8-15,k8-15
    const uint32_t baseA = sA + (uint32_t)(wm * 32 + (lane & 15)) * (LDB * 2)
                              + ((lane >> 4) & 1) * 16;
    // B x4 (per p): m0=n 0-7,k0-7 | m1=n 0-7,k8-15 | m2=n 8-15,k0-7 | m3=n 8-15,k8-15
    const uint32_t baseB = sB + (uint32_t)(wn * 32 + ((lane & 7) | ((lane & 16) >> 1))) * (LDB * 2)
                              + ((lane >> 3) & 1) * 16;

    float acc[2][4][4];
    #pragma unroll
    for (int mt = 0; mt < 2; mt++)
        #pragma unroll
        for (int nt = 0; nt < 4; nt++)
            #pragma unroll
            for (int e = 0; e < 4; e++) acc[mt][nt][e] = 0.f;

    #pragma unroll
    for (int s = 0; s < 8; s++) {            // 8 K-steps of k16
        const uint32_t koff = s * 32;        // 16 bf16 = 32 bytes per step
        uint32_t aR[2][4], bR[2][4];
        #pragma unroll
        for (int mt = 0; mt < 2; mt++)
            LDSM_X4(aR[mt][0], aR[mt][1], aR[mt][2], aR[mt][3],
                    baseA + mt * 16 * (LDB * 2) + koff);
        #pragma unroll
        for (int p = 0; p < 2; p++)
            LDSM_X4(bR[p][0], bR[p][1], bR[p][2], bR[p][3],
                    baseB + p * 16 * (LDB * 2) + koff);
        #pragma unroll
        for (int mt = 0; mt < 2; mt++)
            #pragma unroll
            for (int nt = 0; nt < 4; nt++) {
                const uint32_t b0 = bR[nt >> 1][(nt & 1) * 2];
                const uint32_t b1 = bR[nt >> 1][(nt & 1) * 2 + 1];
                asm volatile(
                    "mma.sync.aligned.m16n8k16.row.col.f32.bf16.bf16.f32 "
                    "{%0,%1,%2,%3}, {%4,%5,%6,%7}, {%8,%9}, {%0,%1,%2,%3};"
                    : "+f"(acc[mt][nt][0]), "+f"(acc[mt][nt][1]),
                      "+f"(acc[mt][nt][2]), "+f"(acc[mt][nt][3])
                    : "r"(aR[mt][0]), "r"(aR[mt][1]), "r"(aR[mt][2]), "r"(aR[mt][3]),
                      "r"(b0), "r"(b1));
            }
    }
    __syncthreads();   // all smem reads done before reuse

    // ---- row max: thread -> quad shfl -> cross-warp via smem ----
    float* pm = (float*)smraw;    // [8(wn)][128]
    #pragma unroll
    for (int mt = 0; mt < 2; mt++) {
        float mlo = -2.f, mhi = -2.f;
        #pragma unroll
        for (int nt = 0; nt < 4; nt++) {
            mlo = fmaxf(mlo, fmaxf(acc[mt][nt][0], acc[mt][nt][1]));
            mhi = fmaxf(mhi, fmaxf(acc[mt][nt][2], acc[mt][nt][3]));
        }
        #pragma unroll
        for (int o = 1; o < 4; o <<= 1) {
            mlo = fmaxf(mlo, __shfl_xor_sync(0xffffffffu, mlo, o));
            mhi = fmaxf(mhi, __shfl_xor_sync(0xffffffffu, mhi, o));
        }
        if ((lane & 3) == 0) {
            int r = wm * 32 + mt * 16 + q;
            pm[wn * 128 + r]     = mlo;
            pm[wn * 128 + r + 8] = mhi;
        }
    }
    __syncthreads();

    if (tid < BM) {
        float m = -2.f;
        #pragma unroll
        for (int j = 0; j < 8; j++) m = fmaxf(m, pm[j * 128 + tid]);
        g_part[blockIdx.x * IPC_C + blockIdx.y * BM + tid] = m;
    }
    __syncthreads();

    // ---- last-block-done fused finalize (lean) ----
    __shared__ int isLast;
    __shared__ float sred;
    if (tid == 0) {
        __threadfence();
        isLast = (atomicAdd(&g_done, 1) == NBLK - 1);
    }
    __syncthreads();
    if (!isLast) return;

    if (tid == 0) { __threadfence(); sred = 0.f; }
    __syncthreads();

    if (tid < IPC_C) {
        float e = -2.f, h = -2.f;
        #pragma unroll
        for (int j = 0; j < ETIL; j++)     e = fmaxf(e, g_part[j * IPC_C + tid]);
        #pragma unroll
        for (int j = ETIL; j < NTIL; j++)  h = fmaxf(h, g_part[j * IPC_C + tid]);
        float loss = log1pf(expf((h - e) * 10.0f));   // 1/SIGMA1 = 10
        #pragma unroll
        for (int o = 16; o; o >>= 1) loss += __shfl_xor_sync(0xffffffffu, loss, o);
        if (lane == 0) atomicAdd(&sred, loss);
    }
    __syncthreads();

    if (tid == 0) {
        out[0] = a_scl[0] * sred * (1.0f / 512.0f);
        g_done = 0;      // reset for the next graph replay
    }
}

extern "C" void kernel_launch(void* const* d_in, const int* in_sizes, int n_in,
                              void* d_out, int out_size) {
    const float* fvec = (const float*)d_in[0];   // [8192,128] f32
    // d_in[1] = Lvec (dead in the reference math)
    const float* a    = (const float*)d_in[2];   // scalar f32
    float* out = (float*)d_out;

    cudaFuncSetAttribute(gemm_kernel,
                         cudaFuncAttributeMaxDynamicSharedMemorySize, SMEM_BYTES);

    prep_kernel<<<N_TOT / 32, 256>>>(fvec);
    gemm_kernel<<<dim3(NTIL, IPC_C / BM), 1024, SMEM_BYTES>>>(a, out);
}